// round 5
// baseline (speedup 1.0000x reference)
#include <cuda_runtime.h>
#include <cuda_bf16.h>
#include <cstdint>

#define IN_F  256
#define OUT_F 128
#define MAX_N 50048
#define MAX_E 800000

// ---------------------------------------------------------------------------
// Scratch (static __device__ — no allocations allowed)
// ---------------------------------------------------------------------------
__device__ float g_h[(size_t)MAX_N * OUT_F];   // normalized transformed features
__device__ int   g_deg[MAX_N];                 // out-degree of src nodes
__device__ int   g_cnt[MAX_N];                 // in-degree of dst nodes
__device__ int   g_off[MAX_N + 1];             // CSR offsets (by dst)
__device__ int   g_pos[MAX_N];                 // bucket cursors
__device__ int   g_srcs[MAX_E];                // src ids grouped by dst
// weight splits, layout [k=256][n=128] bf16 (same as input weight layout)
__device__ __align__(16) unsigned short g_w0[IN_F * OUT_F];
__device__ __align__(16) unsigned short g_w1[IN_F * OUT_F];

// ---------------------------------------------------------------------------
__device__ __forceinline__ uint32_t smem_u32(const void* p) {
    uint32_t a;
    asm("{ .reg .u64 t; cvta.to.shared.u64 t, %1; cvt.u32.u64 %0, t; }" : "=r"(a) : "l"(p));
    return a;
}
__device__ __forceinline__ void ldm_x4(uint32_t* r, uint32_t addr) {
    asm volatile("ldmatrix.sync.aligned.m8n8.x4.shared.b16 {%0,%1,%2,%3}, [%4];"
                 : "=r"(r[0]), "=r"(r[1]), "=r"(r[2]), "=r"(r[3]) : "r"(addr));
}
__device__ __forceinline__ void ldm_x4_t(uint32_t* r, uint32_t addr) {
    asm volatile("ldmatrix.sync.aligned.m8n8.x4.trans.shared.b16 {%0,%1,%2,%3}, [%4];"
                 : "=r"(r[0]), "=r"(r[1]), "=r"(r[2]), "=r"(r[3]) : "r"(addr));
}
__device__ __forceinline__ void mma_bf16(float* d, const uint32_t* a, uint32_t b0, uint32_t b1) {
    asm volatile(
        "mma.sync.aligned.m16n8k16.row.col.f32.bf16.bf16.f32 "
        "{%0,%1,%2,%3}, {%4,%5,%6,%7}, {%8,%9}, {%0,%1,%2,%3};"
        : "+f"(d[0]), "+f"(d[1]), "+f"(d[2]), "+f"(d[3])
        : "r"(a[0]), "r"(a[1]), "r"(a[2]), "r"(a[3]), "r"(b0), "r"(b1));
}
// bf16 split-2: x ~= hi + lo
__device__ __forceinline__ void split_bf16(float x, unsigned short& hi, unsigned short& lo) {
    __nv_bfloat16 h = __float2bfloat16_rn(x);
    float r = x - __bfloat162float(h);
    __nv_bfloat16 l = __float2bfloat16_rn(r);
    hi = __bfloat16_as_ushort(h);
    lo = __bfloat16_as_ushort(l);
}

// ---------------------------------------------------------------------------
// Kernel 1: zero degree + histogram counters
// ---------------------------------------------------------------------------
__global__ void init_kernel(int N) {
    int stride = gridDim.x * blockDim.x;
    int tid = blockIdx.x * blockDim.x + threadIdx.x;
    for (int i = tid; i < N; i += stride) { g_deg[i] = 0; g_cnt[i] = 0; }
}

// ---------------------------------------------------------------------------
// Kernel 2: out-degree(src) + in-degree(dst) in one pass
// ---------------------------------------------------------------------------
__global__ void edge_count_kernel(const int* __restrict__ src,
                                  const int* __restrict__ dst, int E) {
    int stride = gridDim.x * blockDim.x;
    for (int e = blockIdx.x * blockDim.x + threadIdx.x; e < E; e += stride) {
        atomicAdd(&g_deg[src[e]], 1);
        atomicAdd(&g_cnt[dst[e]], 1);
    }
}

// ---------------------------------------------------------------------------
// Kernel 3: split W ([k][n] fp32) into bf16 hi/lo, same layout
// ---------------------------------------------------------------------------
__global__ void wprep_kernel(const float* __restrict__ weight) {
    int idx = blockIdx.x * blockDim.x + threadIdx.x;
    if (idx >= IN_F * OUT_F) return;
    unsigned short hi, lo;
    split_bf16(weight[idx], hi, lo);
    g_w0[idx] = hi;
    g_w1[idx] = lo;
}

// ---------------------------------------------------------------------------
// Kernel 4: single-block exclusive scan of g_cnt -> g_off, g_pos
// ---------------------------------------------------------------------------
__global__ void __launch_bounds__(1024)
scan_kernel(int N, int E) {
    __shared__ int wsum[32];
    int tid = threadIdx.x;
    int lane = tid & 31, w = tid >> 5;
    int chunk = (N + 1023) >> 10;
    int beg = tid * chunk;
    int end = beg + chunk; if (end > N) end = N;
    int s = 0;
    for (int i = beg; i < end; i++) s += g_cnt[i];
    int v = s;
#pragma unroll
    for (int o = 1; o < 32; o <<= 1) {
        int t = __shfl_up_sync(0xffffffffu, v, o);
        if (lane >= o) v += t;
    }
    if (lane == 31) wsum[w] = v;
    __syncthreads();
    if (w == 0) {
        int x = wsum[lane];
#pragma unroll
        for (int o = 1; o < 32; o <<= 1) {
            int t = __shfl_up_sync(0xffffffffu, x, o);
            if (lane >= o) x += t;
        }
        wsum[lane] = x;
    }
    __syncthreads();
    int excl = v - s + (w > 0 ? wsum[w - 1] : 0);
    int run = excl;
    for (int i = beg; i < end; i++) {
        g_off[i] = run; g_pos[i] = run; run += g_cnt[i];
    }
    if (tid == 1023) g_off[N] = E;
}

// ---------------------------------------------------------------------------
// Kernel 5: bucket src ids by dst
// ---------------------------------------------------------------------------
__global__ void bucket_kernel(const int* __restrict__ src,
                              const int* __restrict__ dst, int E) {
    int stride = gridDim.x * blockDim.x;
    for (int e = blockIdx.x * blockDim.x + threadIdx.x; e < E; e += stride) {
        int p = atomicAdd(&g_pos[dst[e]], 1);
        g_srcs[p] = src[e];
    }
}

// ---------------------------------------------------------------------------
// Kernel 6: HMMA GEMM  h = (feat @ W) * (1/max(deg,1))
// CTA: 128m x 128n, 256 threads (8 warps, 4x2: warp -> m32 x n64).
// K in 4 passes of 64. bf16 split-2: D += A0*B0 + A0*B1 + A1*B0.
// smem: A tiles [m][64] bf16 (128B rows, chunk^=(m&7) swizzle),
//       B tiles [k][128] bf16 (256B rows, chunk^=(k&7) swizzle).
// ---------------------------------------------------------------------------
#define KT 64
#define SA0 0
#define SA1 16384
#define SB0 32768
#define SB1 49152
#define GEMM_SMEM 65536

__global__ void __launch_bounds__(256)
gemm_hmma_kernel(const float* __restrict__ feat, int N) {
    extern __shared__ char smem[];
    const uint32_t sb = smem_u32(smem);
    const int tid  = threadIdx.x;
    const int wid  = tid >> 5;
    const int lane = tid & 31;
    const int mw   = wid & 3;        // 0..3 -> m rows [mw*32, +32)
    const int nw   = wid >> 2;       // 0..1 -> n cols [nw*64, +64)
    const int block_row = blockIdx.x * 128;

    float acc[2][8][4];
#pragma unroll
    for (int mt = 0; mt < 2; mt++)
#pragma unroll
        for (int g = 0; g < 8; g++)
#pragma unroll
            for (int c = 0; c < 4; c++) acc[mt][g][c] = 0.f;

    for (int pass = 0; pass < 4; pass++) {
        const int k0 = pass * KT;
        // ---- A: 128 rows x 64 fp32 -> split bf16 hi/lo ----
#pragma unroll
        for (int i = 0; i < 8; i++) {
            int idx = i * 256 + tid;          // 0..2047 (128 rows x 16 float4)
            int r   = idx >> 4;
            int c4  = idx & 15;               // float4 index (=8B bf16 out)
            float4 v = make_float4(0.f, 0.f, 0.f, 0.f);
            int grow = block_row + r;
            if (grow < N)
                v = *(const float4*)(feat + (size_t)grow * IN_F + k0 + c4 * 4);
            unsigned short h0, h1, h2, h3, l0, l1, l2, l3;
            split_bf16(v.x, h0, l0); split_bf16(v.y, h1, l1);
            split_bf16(v.z, h2, l2); split_bf16(v.w, h3, l3);
            uint2 hv, lv;
            hv.x = (uint32_t)h0 | ((uint32_t)h1 << 16);
            hv.y = (uint32_t)h2 | ((uint32_t)h3 << 16);
            lv.x = (uint32_t)l0 | ((uint32_t)l1 << 16);
            lv.y = (uint32_t)l2 | ((uint32_t)l3 << 16);
            int chunk = c4 >> 1, half = c4 & 1;
            uint32_t off = (uint32_t)r * 128 + (uint32_t)((chunk ^ (r & 7)) << 4) + half * 8;
            *(uint2*)(smem + SA0 + off) = hv;
            *(uint2*)(smem + SA1 + off) = lv;
        }
        // ---- B: 64 k-rows x 128 n bf16 from pre-split g_w0/g_w1 ----
#pragma unroll
        for (int i = 0; i < 8; i++) {
            int idx = i * 256 + tid;          // 0..2047 (64 rows x 32 uint2)
            int k   = idx >> 5;
            int c8  = idx & 31;               // 8B units along n
            uint2 v0 = *(const uint2*)&g_w0[(k0 + k) * OUT_F + c8 * 4];
            uint2 v1 = *(const uint2*)&g_w1[(k0 + k) * OUT_F + c8 * 4];
            int chunk = c8 >> 1, half = c8 & 1;
            uint32_t off = (uint32_t)k * 256 + (uint32_t)((chunk ^ (k & 7)) << 4) + half * 8;
            *(uint2*)(smem + SB0 + off) = v0;
            *(uint2*)(smem + SB1 + off) = v1;
        }
        __syncthreads();

#pragma unroll
        for (int ks = 0; ks < 4; ks++) {
            // A fragments (m16k16), non-trans ldmatrix
            uint32_t a0[2][4], a1[2][4];
#pragma unroll
            for (int mt = 0; mt < 2; mt++) {
                int row = mw * 32 + mt * 16 + (lane & 15);
                int chunk = ks * 2 + (lane >> 4);
                uint32_t off = (uint32_t)row * 128 + (uint32_t)((chunk ^ (row & 7)) << 4);
                ldm_x4(a0[mt], sb + SA0 + off);
                ldm_x4(a1[mt], sb + SA1 + off);
            }
            // B fragments (k16n16 per group), trans ldmatrix
            uint32_t b0[8][2], b1[8][2];
#pragma unroll
            for (int g16 = 0; g16 < 4; g16++) {
                int t = lane >> 3;
                int krow = ks * 16 + ((t & 1) << 3) + (lane & 7);
                int chunk = nw * 8 + g16 * 2 + (t >> 1);
                uint32_t off = (uint32_t)krow * 256 + (uint32_t)((chunk ^ (krow & 7)) << 4);
                uint32_t r0[4], r1[4];
                ldm_x4_t(r0, sb + SB0 + off);
                ldm_x4_t(r1, sb + SB1 + off);
                b0[g16 * 2 + 0][0] = r0[0]; b0[g16 * 2 + 0][1] = r0[1];
                b0[g16 * 2 + 1][0] = r0[2]; b0[g16 * 2 + 1][1] = r0[3];
                b1[g16 * 2 + 0][0] = r1[0]; b1[g16 * 2 + 0][1] = r1[1];
                b1[g16 * 2 + 1][0] = r1[2]; b1[g16 * 2 + 1][1] = r1[3];
            }
#pragma unroll
            for (int mt = 0; mt < 2; mt++)
#pragma unroll
                for (int g = 0; g < 8; g++) {
                    mma_bf16(acc[mt][g], a0[mt], b0[g][0], b0[g][1]);
                    mma_bf16(acc[mt][g], a0[mt], b1[g][0], b1[g][1]);
                    mma_bf16(acc[mt][g], a1[mt], b0[g][0], b0[g][1]);
                }
        }
        __syncthreads();
    }

    // ---- epilogue: scale by 1/max(deg,1), store g_h ----
#pragma unroll
    for (int mt = 0; mt < 2; mt++) {
        int row0 = block_row + mw * 32 + mt * 16 + (lane >> 2);
        int row1 = row0 + 8;
        float n0 = (row0 < N) ? 1.0f / fmaxf((float)g_deg[row0], 1.0f) : 0.f;
        float n1 = (row1 < N) ? 1.0f / fmaxf((float)g_deg[row1], 1.0f) : 0.f;
#pragma unroll
        for (int g = 0; g < 8; g++) {
            int col = nw * 64 + g * 8 + (lane & 3) * 2;
            if (row0 < N)
                *(float2*)(g_h + (size_t)row0 * OUT_F + col) =
                    make_float2(acc[mt][g][0] * n0, acc[mt][g][1] * n0);
            if (row1 < N)
                *(float2*)(g_h + (size_t)row1 * OUT_F + col) =
                    make_float2(acc[mt][g][2] * n1, acc[mt][g][3] * n1);
        }
    }
}

// ---------------------------------------------------------------------------
// Kernel 7: gather  out[n] = sum_{e: dst=n} h[src[e]] + bias   (one warp/node)
// ---------------------------------------------------------------------------
__global__ void __launch_bounds__(256)
gather_kernel(const float* __restrict__ bias, float* __restrict__ out, int N) {
    const int lane = threadIdx.x & 31;
    const int node = (blockIdx.x * blockDim.x + threadIdx.x) >> 5;
    if (node >= N) return;
    const int beg = g_off[node];
    const int end = g_off[node + 1];

    float4 acc = make_float4(0.f, 0.f, 0.f, 0.f);
    for (int b = beg; b < end; b += 32) {
        int idx = b + lane;
        int s = (idx < end) ? g_srcs[idx] : 0;
        int cnt = end - b; if (cnt > 32) cnt = 32;
        for (int j = 0; j < cnt; j++) {
            int sj = __shfl_sync(0xffffffffu, s, j);
            float4 v = *((const float4*)(g_h + (size_t)sj * OUT_F) + lane);
            acc.x += v.x; acc.y += v.y; acc.z += v.z; acc.w += v.w;
        }
    }
    float4 b4 = *((const float4*)bias + lane);
    *((float4*)(out + (size_t)node * OUT_F) + lane) =
        make_float4(acc.x + b4.x, acc.y + b4.y, acc.z + b4.z, acc.w + b4.w);
}

// ---------------------------------------------------------------------------
extern "C" void kernel_launch(void* const* d_in, const int* in_sizes, int n_in,
                              void* d_out, int out_size) {
    const float* feat   = (const float*)d_in[0];
    const float* weight = (const float*)d_in[1];
    const float* bias   = (const float*)d_in[2];
    const int*   src    = (const int*)d_in[3];
    const int*   dst    = (const int*)d_in[4];
    float* out = (float*)d_out;

    const int N = in_sizes[0] / IN_F;   // 50000
    const int E = in_sizes[3];          // 800000

    cudaFuncSetAttribute(gemm_hmma_kernel,
                         cudaFuncAttributeMaxDynamicSharedMemorySize, GEMM_SMEM);

    init_kernel<<<256, 256>>>(N);
    edge_count_kernel<<<512, 256>>>(src, dst, E);
    wprep_kernel<<<(IN_F * OUT_F + 255) / 256, 256>>>(weight);
    scan_kernel<<<1, 1024>>>(N, E);
    bucket_kernel<<<512, 256>>>(src, dst, E);
    gemm_hmma_kernel<<<(N + 127) / 128, 256, GEMM_SMEM>>>(feat, N);
    gather_kernel<<<(N * 32 + 255) / 256, 256>>>(bias, out, N);
}

// round 6
// speedup vs baseline: 1.5729x; 1.5729x over previous
#include <cuda_runtime.h>
#include <cuda_bf16.h>
#include <cstdint>

#define IN_F  256
#define OUT_F 128
#define MAX_N 50048
#define MAX_E 800000
#define SCAN_B 1024
#define SCAN_NB ((MAX_N + SCAN_B - 1) / SCAN_B)   // 49

// ---------------------------------------------------------------------------
// Scratch (static __device__ — no allocations allowed)
// ---------------------------------------------------------------------------
__device__ float g_h[(size_t)MAX_N * OUT_F];   // normalized transformed features
__device__ int   g_deg[MAX_N];                 // out-degree of src nodes
__device__ int   g_cnt[MAX_N];                 // in-degree of dst nodes
__device__ int   g_off[MAX_N + 1];             // CSR offsets (by dst)
__device__ int   g_pos[MAX_N];                 // bucket cursors
__device__ int   g_srcs[MAX_E];                // src ids grouped by dst
__device__ int   g_bsum[SCAN_NB];              // per-block scan totals
__device__ int   g_bbase[SCAN_NB];             // per-block scan bases
// weight splits, layout [k=256][n=128] bf16
__device__ __align__(16) unsigned short g_w0[IN_F * OUT_F];
__device__ __align__(16) unsigned short g_w1[IN_F * OUT_F];

// ---------------------------------------------------------------------------
__device__ __forceinline__ uint32_t smem_u32(const void* p) {
    uint32_t a;
    asm("{ .reg .u64 t; cvta.to.shared.u64 t, %1; cvt.u32.u64 %0, t; }" : "=r"(a) : "l"(p));
    return a;
}
__device__ __forceinline__ void ldm_x4(uint32_t* r, uint32_t addr) {
    asm volatile("ldmatrix.sync.aligned.m8n8.x4.shared.b16 {%0,%1,%2,%3}, [%4];"
                 : "=r"(r[0]), "=r"(r[1]), "=r"(r[2]), "=r"(r[3]) : "r"(addr));
}
__device__ __forceinline__ void ldm_x4_t(uint32_t* r, uint32_t addr) {
    asm volatile("ldmatrix.sync.aligned.m8n8.x4.trans.shared.b16 {%0,%1,%2,%3}, [%4];"
                 : "=r"(r[0]), "=r"(r[1]), "=r"(r[2]), "=r"(r[3]) : "r"(addr));
}
__device__ __forceinline__ void mma_bf16(float* d, const uint32_t* a, uint32_t b0, uint32_t b1) {
    asm volatile(
        "mma.sync.aligned.m16n8k16.row.col.f32.bf16.bf16.f32 "
        "{%0,%1,%2,%3}, {%4,%5,%6,%7}, {%8,%9}, {%0,%1,%2,%3};"
        : "+f"(d[0]), "+f"(d[1]), "+f"(d[2]), "+f"(d[3])
        : "r"(a[0]), "r"(a[1]), "r"(a[2]), "r"(a[3]), "r"(b0), "r"(b1));
}
__device__ __forceinline__ void split_bf16(float x, unsigned short& hi, unsigned short& lo) {
    __nv_bfloat16 h = __float2bfloat16_rn(x);
    float r = x - __bfloat162float(h);
    __nv_bfloat16 l = __float2bfloat16_rn(r);
    hi = __bfloat16_as_ushort(h);
    lo = __bfloat16_as_ushort(l);
}

// ---------------------------------------------------------------------------
// Kernel 1: zero degree + histogram counters
// ---------------------------------------------------------------------------
__global__ void init_kernel(int N) {
    int stride = gridDim.x * blockDim.x;
    int tid = blockIdx.x * blockDim.x + threadIdx.x;
    for (int i = tid; i < N; i += stride) { g_deg[i] = 0; g_cnt[i] = 0; }
}

// ---------------------------------------------------------------------------
// Kernel 2: out-degree(src) + in-degree(dst) in one pass
// ---------------------------------------------------------------------------
__global__ void edge_count_kernel(const int* __restrict__ src,
                                  const int* __restrict__ dst, int E) {
    int stride = gridDim.x * blockDim.x;
    for (int e = blockIdx.x * blockDim.x + threadIdx.x; e < E; e += stride) {
        atomicAdd(&g_deg[src[e]], 1);
        atomicAdd(&g_cnt[dst[e]], 1);
    }
}

// ---------------------------------------------------------------------------
// Kernel 3: split W ([k][n] fp32) into bf16 hi/lo
// ---------------------------------------------------------------------------
__global__ void wprep_kernel(const float* __restrict__ weight) {
    int idx = blockIdx.x * blockDim.x + threadIdx.x;
    if (idx >= IN_F * OUT_F) return;
    unsigned short hi, lo;
    split_bf16(weight[idx], hi, lo);
    g_w0[idx] = hi;
    g_w1[idx] = lo;
}

// ---------------------------------------------------------------------------
// Kernel 4a: per-block exclusive scan of g_cnt (local) + block totals
// ---------------------------------------------------------------------------
__global__ void __launch_bounds__(SCAN_B)
scanA_kernel(int N) {
    __shared__ int wsum[32];
    int i = blockIdx.x * SCAN_B + threadIdx.x;
    int lane = threadIdx.x & 31, w = threadIdx.x >> 5;
    int v = (i < N) ? g_cnt[i] : 0;
    int inc = v;
#pragma unroll
    for (int o = 1; o < 32; o <<= 1) {
        int t = __shfl_up_sync(0xffffffffu, inc, o);
        if (lane >= o) inc += t;
    }
    if (lane == 31) wsum[w] = inc;
    __syncthreads();
    if (w == 0) {
        int x = wsum[lane];
#pragma unroll
        for (int o = 1; o < 32; o <<= 1) {
            int t = __shfl_up_sync(0xffffffffu, x, o);
            if (lane >= o) x += t;
        }
        wsum[lane] = x;
    }
    __syncthreads();
    int base = (w > 0) ? wsum[w - 1] : 0;
    int excl = base + inc - v;
    if (i < N) g_off[i] = excl;
    if (threadIdx.x == SCAN_B - 1) g_bsum[blockIdx.x] = base + inc;
}

// ---------------------------------------------------------------------------
// Kernel 4b: exclusive scan of block totals (tiny, serial on thread 0)
// ---------------------------------------------------------------------------
__global__ void scanB_kernel(int nb) {
    __shared__ int s[SCAN_NB];
    if (threadIdx.x < nb) s[threadIdx.x] = g_bsum[threadIdx.x];
    __syncthreads();
    if (threadIdx.x == 0) {
        int run = 0;
        for (int b = 0; b < nb; b++) { int t = s[b]; s[b] = run; run += t; }
    }
    __syncthreads();
    if (threadIdx.x < nb) g_bbase[threadIdx.x] = s[threadIdx.x];
}

// ---------------------------------------------------------------------------
// Kernel 4c: add block bases; mirror into g_pos; terminate offsets
// ---------------------------------------------------------------------------
__global__ void __launch_bounds__(SCAN_B)
scanC_kernel(int N, int E) {
    int i = blockIdx.x * SCAN_B + threadIdx.x;
    if (i < N) {
        int o = g_off[i] + g_bbase[blockIdx.x];
        g_off[i] = o;
        g_pos[i] = o;
    }
    if (i == 0) g_off[N] = E;
}

// ---------------------------------------------------------------------------
// Kernel 5: bucket src ids by dst
// ---------------------------------------------------------------------------
__global__ void bucket_kernel(const int* __restrict__ src,
                              const int* __restrict__ dst, int E) {
    int stride = gridDim.x * blockDim.x;
    for (int e = blockIdx.x * blockDim.x + threadIdx.x; e < E; e += stride) {
        int p = atomicAdd(&g_pos[dst[e]], 1);
        g_srcs[p] = src[e];
    }
}

// ---------------------------------------------------------------------------
// Kernel 6: HMMA GEMM  h = (feat @ W) * (1/max(deg,1))   (unchanged from R4)
// ---------------------------------------------------------------------------
#define KT 64
#define SA0 0
#define SA1 16384
#define SB0 32768
#define SB1 49152
#define GEMM_SMEM 65536

__global__ void __launch_bounds__(256)
gemm_hmma_kernel(const float* __restrict__ feat, int N) {
    extern __shared__ char smem[];
    const uint32_t sb = smem_u32(smem);
    const int tid  = threadIdx.x;
    const int wid  = tid >> 5;
    const int lane = tid & 31;
    const int mw   = wid & 3;
    const int nw   = wid >> 2;
    const int block_row = blockIdx.x * 128;

    float acc[2][8][4];
#pragma unroll
    for (int mt = 0; mt < 2; mt++)
#pragma unroll
        for (int g = 0; g < 8; g++)
#pragma unroll
            for (int c = 0; c < 4; c++) acc[mt][g][c] = 0.f;

    for (int pass = 0; pass < 4; pass++) {
        const int k0 = pass * KT;
#pragma unroll
        for (int i = 0; i < 8; i++) {
            int idx = i * 256 + tid;
            int r   = idx >> 4;
            int c4  = idx & 15;
            float4 v = make_float4(0.f, 0.f, 0.f, 0.f);
            int grow = block_row + r;
            if (grow < N)
                v = *(const float4*)(feat + (size_t)grow * IN_F + k0 + c4 * 4);
            unsigned short h0, h1, h2, h3, l0, l1, l2, l3;
            split_bf16(v.x, h0, l0); split_bf16(v.y, h1, l1);
            split_bf16(v.z, h2, l2); split_bf16(v.w, h3, l3);
            uint2 hv, lv;
            hv.x = (uint32_t)h0 | ((uint32_t)h1 << 16);
            hv.y = (uint32_t)h2 | ((uint32_t)h3 << 16);
            lv.x = (uint32_t)l0 | ((uint32_t)l1 << 16);
            lv.y = (uint32_t)l2 | ((uint32_t)l3 << 16);
            int chunk = c4 >> 1, half = c4 & 1;
            uint32_t off = (uint32_t)r * 128 + (uint32_t)((chunk ^ (r & 7)) << 4) + half * 8;
            *(uint2*)(smem + SA0 + off) = hv;
            *(uint2*)(smem + SA1 + off) = lv;
        }
#pragma unroll
        for (int i = 0; i < 8; i++) {
            int idx = i * 256 + tid;
            int k   = idx >> 5;
            int c8  = idx & 31;
            uint2 v0 = *(const uint2*)&g_w0[(k0 + k) * OUT_F + c8 * 4];
            uint2 v1 = *(const uint2*)&g_w1[(k0 + k) * OUT_F + c8 * 4];
            int chunk = c8 >> 1, half = c8 & 1;
            uint32_t off = (uint32_t)k * 256 + (uint32_t)((chunk ^ (k & 7)) << 4) + half * 8;
            *(uint2*)(smem + SB0 + off) = v0;
            *(uint2*)(smem + SB1 + off) = v1;
        }
        __syncthreads();

#pragma unroll
        for (int ks = 0; ks < 4; ks++) {
            uint32_t a0[2][4], a1[2][4];
#pragma unroll
            for (int mt = 0; mt < 2; mt++) {
                int row = mw * 32 + mt * 16 + (lane & 15);
                int chunk = ks * 2 + (lane >> 4);
                uint32_t off = (uint32_t)row * 128 + (uint32_t)((chunk ^ (row & 7)) << 4);
                ldm_x4(a0[mt], sb + SA0 + off);
                ldm_x4(a1[mt], sb + SA1 + off);
            }
            uint32_t b0[8][2], b1[8][2];
#pragma unroll
            for (int g16 = 0; g16 < 4; g16++) {
                int t = lane >> 3;
                int krow = ks * 16 + ((t & 1) << 3) + (lane & 7);
                int chunk = nw * 8 + g16 * 2 + (t >> 1);
                uint32_t off = (uint32_t)krow * 256 + (uint32_t)((chunk ^ (krow & 7)) << 4);
                uint32_t r0[4], r1[4];
                ldm_x4_t(r0, sb + SB0 + off);
                ldm_x4_t(r1, sb + SB1 + off);
                b0[g16 * 2 + 0][0] = r0[0]; b0[g16 * 2 + 0][1] = r0[1];
                b0[g16 * 2 + 1][0] = r0[2]; b0[g16 * 2 + 1][1] = r0[3];
                b1[g16 * 2 + 0][0] = r1[0]; b1[g16 * 2 + 0][1] = r1[1];
                b1[g16 * 2 + 1][0] = r1[2]; b1[g16 * 2 + 1][1] = r1[3];
            }
#pragma unroll
            for (int mt = 0; mt < 2; mt++)
#pragma unroll
                for (int g = 0; g < 8; g++) {
                    mma_bf16(acc[mt][g], a0[mt], b0[g][0], b0[g][1]);
                    mma_bf16(acc[mt][g], a0[mt], b1[g][0], b1[g][1]);
                    mma_bf16(acc[mt][g], a1[mt], b0[g][0], b0[g][1]);
                }
        }
        __syncthreads();
    }

#pragma unroll
    for (int mt = 0; mt < 2; mt++) {
        int row0 = block_row + mw * 32 + mt * 16 + (lane >> 2);
        int row1 = row0 + 8;
        float n0 = (row0 < N) ? 1.0f / fmaxf((float)g_deg[row0], 1.0f) : 0.f;
        float n1 = (row1 < N) ? 1.0f / fmaxf((float)g_deg[row1], 1.0f) : 0.f;
#pragma unroll
        for (int g = 0; g < 8; g++) {
            int col = nw * 64 + g * 8 + (lane & 3) * 2;
            if (row0 < N)
                *(float2*)(g_h + (size_t)row0 * OUT_F + col) =
                    make_float2(acc[mt][g][0] * n0, acc[mt][g][1] * n0);
            if (row1 < N)
                *(float2*)(g_h + (size_t)row1 * OUT_F + col) =
                    make_float2(acc[mt][g][2] * n1, acc[mt][g][3] * n1);
        }
    }
}

// ---------------------------------------------------------------------------
// Kernel 7: gather  out[n] = sum_{e: dst=n} h[src[e]] + bias   (one warp/node)
// ---------------------------------------------------------------------------
__global__ void __launch_bounds__(256)
gather_kernel(const float* __restrict__ bias, float* __restrict__ out, int N) {
    const int lane = threadIdx.x & 31;
    const int node = (blockIdx.x * blockDim.x + threadIdx.x) >> 5;
    if (node >= N) return;
    const int beg = g_off[node];
    const int end = g_off[node + 1];

    float4 acc = make_float4(0.f, 0.f, 0.f, 0.f);
    for (int b = beg; b < end; b += 32) {
        int idx = b + lane;
        int s = (idx < end) ? g_srcs[idx] : 0;
        int cnt = end - b; if (cnt > 32) cnt = 32;
        for (int j = 0; j < cnt; j++) {
            int sj = __shfl_sync(0xffffffffu, s, j);
            float4 v = *((const float4*)(g_h + (size_t)sj * OUT_F) + lane);
            acc.x += v.x; acc.y += v.y; acc.z += v.z; acc.w += v.w;
        }
    }
    float4 b4 = *((const float4*)bias + lane);
    *((float4*)(out + (size_t)node * OUT_F) + lane) =
        make_float4(acc.x + b4.x, acc.y + b4.y, acc.z + b4.z, acc.w + b4.w);
}

// ---------------------------------------------------------------------------
extern "C" void kernel_launch(void* const* d_in, const int* in_sizes, int n_in,
                              void* d_out, int out_size) {
    const float* feat   = (const float*)d_in[0];
    const float* weight = (const float*)d_in[1];
    const float* bias   = (const float*)d_in[2];
    const int*   src    = (const int*)d_in[3];
    const int*   dst    = (const int*)d_in[4];
    float* out = (float*)d_out;

    const int N = in_sizes[0] / IN_F;   // 50000
    const int E = in_sizes[3];          // 800000
    const int nb = (N + SCAN_B - 1) / SCAN_B;

    cudaFuncSetAttribute(gemm_hmma_kernel,
                         cudaFuncAttributeMaxDynamicSharedMemorySize, GEMM_SMEM);

    init_kernel<<<256, 256>>>(N);
    edge_count_kernel<<<512, 256>>>(src, dst, E);
    wprep_kernel<<<(IN_F * OUT_F + 255) / 256, 256>>>(weight);
    scanA_kernel<<<nb, SCAN_B>>>(N);
    scanB_kernel<<<1, 64>>>(nb);
    scanC_kernel<<<nb, SCAN_B>>>(N, E);
    bucket_kernel<<<512, 256>>>(src, dst, E);
    gemm_hmma_kernel<<<(N + 127) / 128, 256, GEMM_SMEM>>>(feat, N);
    gather_kernel<<<(N * 32 + 255) / 256, 256>>>(bias, out, N);
}

// round 7
// speedup vs baseline: 1.8528x; 1.1780x over previous
#include <cuda_runtime.h>
#include <cuda_bf16.h>
#include <cuda_fp16.h>
#include <cstdint>

#define IN_F  256
#define OUT_F 128
#define MAX_N 50048
#define MAX_E 800000
#define SCAN_B 1024
#define SCAN_NB ((MAX_N + SCAN_B - 1) / SCAN_B)   // 49

// ---------------------------------------------------------------------------
// Scratch (static __device__ — no allocations allowed)
// ---------------------------------------------------------------------------
__device__ __align__(16) __half g_h[(size_t)MAX_N * OUT_F];  // normalized transformed feats (fp16)
__device__ int   g_deg[MAX_N];                 // out-degree of src nodes
__device__ int   g_cnt[MAX_N];                 // in-degree of dst nodes
__device__ int   g_off[MAX_N + 1];             // CSR offsets (by dst)
__device__ int   g_pos[MAX_N];                 // bucket cursors
__device__ int   g_srcs[MAX_E];                // src ids grouped by dst
__device__ int   g_bsum[SCAN_NB];              // per-block scan totals
__device__ int   g_bbase[SCAN_NB];             // per-block scan bases
// weight splits, layout [k=256][n=128] bf16
__device__ __align__(16) unsigned short g_w0[IN_F * OUT_F];
__device__ __align__(16) unsigned short g_w1[IN_F * OUT_F];

// ---------------------------------------------------------------------------
__device__ __forceinline__ uint32_t smem_u32(const void* p) {
    uint32_t a;
    asm("{ .reg .u64 t; cvta.to.shared.u64 t, %1; cvt.u32.u64 %0, t; }" : "=r"(a) : "l"(p));
    return a;
}
__device__ __forceinline__ void ldm_x4(uint32_t* r, uint32_t addr) {
    asm volatile("ldmatrix.sync.aligned.m8n8.x4.shared.b16 {%0,%1,%2,%3}, [%4];"
                 : "=r"(r[0]), "=r"(r[1]), "=r"(r[2]), "=r"(r[3]) : "r"(addr));
}
__device__ __forceinline__ void ldm_x4_t(uint32_t* r, uint32_t addr) {
    asm volatile("ldmatrix.sync.aligned.m8n8.x4.trans.shared.b16 {%0,%1,%2,%3}, [%4];"
                 : "=r"(r[0]), "=r"(r[1]), "=r"(r[2]), "=r"(r[3]) : "r"(addr));
}
__device__ __forceinline__ void mma_bf16(float* d, const uint32_t* a, uint32_t b0, uint32_t b1) {
    asm volatile(
        "mma.sync.aligned.m16n8k16.row.col.f32.bf16.bf16.f32 "
        "{%0,%1,%2,%3}, {%4,%5,%6,%7}, {%8,%9}, {%0,%1,%2,%3};"
        : "+f"(d[0]), "+f"(d[1]), "+f"(d[2]), "+f"(d[3])
        : "r"(a[0]), "r"(a[1]), "r"(a[2]), "r"(a[3]), "r"(b0), "r"(b1));
}
__device__ __forceinline__ void split_bf16(float x, unsigned short& hi, unsigned short& lo) {
    __nv_bfloat16 h = __float2bfloat16_rn(x);
    float r = x - __bfloat162float(h);
    __nv_bfloat16 l = __float2bfloat16_rn(r);
    hi = __bfloat16_as_ushort(h);
    lo = __bfloat16_as_ushort(l);
}

// ---------------------------------------------------------------------------
// Kernel 1: zero degree + histogram counters
// ---------------------------------------------------------------------------
__global__ void init_kernel(int N) {
    int stride = gridDim.x * blockDim.x;
    int tid = blockIdx.x * blockDim.x + threadIdx.x;
    for (int i = tid; i < N; i += stride) { g_deg[i] = 0; g_cnt[i] = 0; }
}

// ---------------------------------------------------------------------------
// Kernel 2: out-degree(src) + in-degree(dst) in one pass
// ---------------------------------------------------------------------------
__global__ void edge_count_kernel(const int* __restrict__ src,
                                  const int* __restrict__ dst, int E) {
    int stride = gridDim.x * blockDim.x;
    for (int e = blockIdx.x * blockDim.x + threadIdx.x; e < E; e += stride) {
        atomicAdd(&g_deg[src[e]], 1);
        atomicAdd(&g_cnt[dst[e]], 1);
    }
}

// ---------------------------------------------------------------------------
// Kernel 3: split W ([k][n] fp32) into bf16 hi/lo
// ---------------------------------------------------------------------------
__global__ void wprep_kernel(const float* __restrict__ weight) {
    int idx = blockIdx.x * blockDim.x + threadIdx.x;
    if (idx >= IN_F * OUT_F) return;
    unsigned short hi, lo;
    split_bf16(weight[idx], hi, lo);
    g_w0[idx] = hi;
    g_w1[idx] = lo;
}

// ---------------------------------------------------------------------------
// Kernel 4a/4b/4c: hierarchical exclusive scan of g_cnt -> g_off, g_pos
// ---------------------------------------------------------------------------
__global__ void __launch_bounds__(SCAN_B)
scanA_kernel(int N) {
    __shared__ int wsum[32];
    int i = blockIdx.x * SCAN_B + threadIdx.x;
    int lane = threadIdx.x & 31, w = threadIdx.x >> 5;
    int v = (i < N) ? g_cnt[i] : 0;
    int inc = v;
#pragma unroll
    for (int o = 1; o < 32; o <<= 1) {
        int t = __shfl_up_sync(0xffffffffu, inc, o);
        if (lane >= o) inc += t;
    }
    if (lane == 31) wsum[w] = inc;
    __syncthreads();
    if (w == 0) {
        int x = wsum[lane];
#pragma unroll
        for (int o = 1; o < 32; o <<= 1) {
            int t = __shfl_up_sync(0xffffffffu, x, o);
            if (lane >= o) x += t;
        }
        wsum[lane] = x;
    }
    __syncthreads();
    int base = (w > 0) ? wsum[w - 1] : 0;
    int excl = base + inc - v;
    if (i < N) g_off[i] = excl;
    if (threadIdx.x == SCAN_B - 1) g_bsum[blockIdx.x] = base + inc;
}

__global__ void scanB_kernel(int nb) {
    __shared__ int s[SCAN_NB];
    if (threadIdx.x < nb) s[threadIdx.x] = g_bsum[threadIdx.x];
    __syncthreads();
    if (threadIdx.x == 0) {
        int run = 0;
        for (int b = 0; b < nb; b++) { int t = s[b]; s[b] = run; run += t; }
    }
    __syncthreads();
    if (threadIdx.x < nb) g_bbase[threadIdx.x] = s[threadIdx.x];
}

__global__ void __launch_bounds__(SCAN_B)
scanC_kernel(int N, int E) {
    int i = blockIdx.x * SCAN_B + threadIdx.x;
    if (i < N) {
        int o = g_off[i] + g_bbase[blockIdx.x];
        g_off[i] = o;
        g_pos[i] = o;
    }
    if (i == 0) g_off[N] = E;
}

// ---------------------------------------------------------------------------
// Kernel 5: bucket src ids by dst
// ---------------------------------------------------------------------------
__global__ void bucket_kernel(const int* __restrict__ src,
                              const int* __restrict__ dst, int E) {
    int stride = gridDim.x * blockDim.x;
    for (int e = blockIdx.x * blockDim.x + threadIdx.x; e < E; e += stride) {
        int p = atomicAdd(&g_pos[dst[e]], 1);
        g_srcs[p] = src[e];
    }
}

// ---------------------------------------------------------------------------
// Kernel 6: HMMA GEMM  h = (feat @ W) * (1/max(deg,1)), fp16 output,
// A-tile register prefetch across K-passes.
// ---------------------------------------------------------------------------
#define KT 64
#define SA0 0
#define SA1 16384
#define SB0 32768
#define SB1 49152
#define GEMM_SMEM 65536

__device__ __forceinline__ void load_a_regs(float4* va, const float* __restrict__ feat,
                                            int block_row, int k0, int tid, int N) {
#pragma unroll
    for (int i = 0; i < 8; i++) {
        int idx = i * 256 + tid;
        int r   = idx >> 4;
        int c4  = idx & 15;
        int grow = block_row + r;
        va[i] = make_float4(0.f, 0.f, 0.f, 0.f);
        if (grow < N)
            va[i] = *(const float4*)(feat + (size_t)grow * IN_F + k0 + c4 * 4);
    }
}

__global__ void __launch_bounds__(256)
gemm_hmma_kernel(const float* __restrict__ feat, int N) {
    extern __shared__ char smem[];
    const uint32_t sb = smem_u32(smem);
    const int tid  = threadIdx.x;
    const int wid  = tid >> 5;
    const int lane = tid & 31;
    const int mw   = wid & 3;
    const int nw   = wid >> 2;
    const int block_row = blockIdx.x * 128;

    float acc[2][8][4];
#pragma unroll
    for (int mt = 0; mt < 2; mt++)
#pragma unroll
        for (int g = 0; g < 8; g++)
#pragma unroll
            for (int c = 0; c < 4; c++) acc[mt][g][c] = 0.f;

    float4 va[8];
    load_a_regs(va, feat, block_row, 0, tid, N);

    for (int pass = 0; pass < 4; pass++) {
        const int k0 = pass * KT;
        // ---- split prefetched A regs -> smem ----
#pragma unroll
        for (int i = 0; i < 8; i++) {
            int idx = i * 256 + tid;
            int r   = idx >> 4;
            int c4  = idx & 15;
            float4 v = va[i];
            unsigned short h0, h1, h2, h3, l0, l1, l2, l3;
            split_bf16(v.x, h0, l0); split_bf16(v.y, h1, l1);
            split_bf16(v.z, h2, l2); split_bf16(v.w, h3, l3);
            uint2 hv, lv;
            hv.x = (uint32_t)h0 | ((uint32_t)h1 << 16);
            hv.y = (uint32_t)h2 | ((uint32_t)h3 << 16);
            lv.x = (uint32_t)l0 | ((uint32_t)l1 << 16);
            lv.y = (uint32_t)l2 | ((uint32_t)l3 << 16);
            int chunk = c4 >> 1, half = c4 & 1;
            uint32_t off = (uint32_t)r * 128 + (uint32_t)((chunk ^ (r & 7)) << 4) + half * 8;
            *(uint2*)(smem + SA0 + off) = hv;
            *(uint2*)(smem + SA1 + off) = lv;
        }
        // ---- B: 64 k-rows x 128 n bf16 from pre-split g_w0/g_w1 (L2-hot) ----
#pragma unroll
        for (int i = 0; i < 8; i++) {
            int idx = i * 256 + tid;
            int k   = idx >> 5;
            int c8  = idx & 31;
            uint2 v0 = *(const uint2*)&g_w0[(k0 + k) * OUT_F + c8 * 4];
            uint2 v1 = *(const uint2*)&g_w1[(k0 + k) * OUT_F + c8 * 4];
            int chunk = c8 >> 1, half = c8 & 1;
            uint32_t off = (uint32_t)k * 256 + (uint32_t)((chunk ^ (k & 7)) << 4) + half * 8;
            *(uint2*)(smem + SB0 + off) = v0;
            *(uint2*)(smem + SB1 + off) = v1;
        }
        __syncthreads();

        // ---- prefetch next pass A (overlaps with MMA below) ----
        if (pass < 3)
            load_a_regs(va, feat, block_row, k0 + KT, tid, N);

#pragma unroll
        for (int ks = 0; ks < 4; ks++) {
            uint32_t a0[2][4], a1[2][4];
#pragma unroll
            for (int mt = 0; mt < 2; mt++) {
                int row = mw * 32 + mt * 16 + (lane & 15);
                int chunk = ks * 2 + (lane >> 4);
                uint32_t off = (uint32_t)row * 128 + (uint32_t)((chunk ^ (row & 7)) << 4);
                ldm_x4(a0[mt], sb + SA0 + off);
                ldm_x4(a1[mt], sb + SA1 + off);
            }
            uint32_t b0[8][2], b1[8][2];
#pragma unroll
            for (int g16 = 0; g16 < 4; g16++) {
                int t = lane >> 3;
                int krow = ks * 16 + ((t & 1) << 3) + (lane & 7);
                int chunk = nw * 8 + g16 * 2 + (t >> 1);
                uint32_t off = (uint32_t)krow * 256 + (uint32_t)((chunk ^ (krow & 7)) << 4);
                uint32_t r0[4], r1[4];
                ldm_x4_t(r0, sb + SB0 + off);
                ldm_x4_t(r1, sb + SB1 + off);
                b0[g16 * 2 + 0][0] = r0[0]; b0[g16 * 2 + 0][1] = r0[1];
                b0[g16 * 2 + 1][0] = r0[2]; b0[g16 * 2 + 1][1] = r0[3];
                b1[g16 * 2 + 0][0] = r1[0]; b1[g16 * 2 + 0][1] = r1[1];
                b1[g16 * 2 + 1][0] = r1[2]; b1[g16 * 2 + 1][1] = r1[3];
            }
#pragma unroll
            for (int mt = 0; mt < 2; mt++)
#pragma unroll
                for (int g = 0; g < 8; g++) {
                    mma_bf16(acc[mt][g], a0[mt], b0[g][0], b0[g][1]);
                    mma_bf16(acc[mt][g], a0[mt], b1[g][0], b1[g][1]);
                    mma_bf16(acc[mt][g], a1[mt], b0[g][0], b0[g][1]);
                }
        }
        __syncthreads();
    }

    // ---- epilogue: scale by 1/max(deg,1), store fp16 h ----
#pragma unroll
    for (int mt = 0; mt < 2; mt++) {
        int row0 = block_row + mw * 32 + mt * 16 + (lane >> 2);
        int row1 = row0 + 8;
        float n0 = (row0 < N) ? 1.0f / fmaxf((float)g_deg[row0], 1.0f) : 0.f;
        float n1 = (row1 < N) ? 1.0f / fmaxf((float)g_deg[row1], 1.0f) : 0.f;
#pragma unroll
        for (int g = 0; g < 8; g++) {
            int col = nw * 64 + g * 8 + (lane & 3) * 2;
            if (row0 < N)
                *(__half2*)(g_h + (size_t)row0 * OUT_F + col) =
                    __floats2half2_rn(acc[mt][g][0] * n0, acc[mt][g][1] * n0);
            if (row1 < N)
                *(__half2*)(g_h + (size_t)row1 * OUT_F + col) =
                    __floats2half2_rn(acc[mt][g][2] * n1, acc[mt][g][3] * n1);
        }
    }
}

// ---------------------------------------------------------------------------
// Kernel 7: gather  out[n] = sum_{e: dst=n} h[src[e]] + bias   (one warp/node)
// fp16 rows (256B), lane covers 4 cols (8B), j-loop unrolled x4 for MLP.
// ---------------------------------------------------------------------------
__device__ __forceinline__ void acc_row(float4& acc, int s, int lane) {
    uint2 u = *((const uint2*)(g_h + (size_t)s * OUT_F) + lane);
    float2 f0 = __half22float2(*(__half2*)&u.x);
    float2 f1 = __half22float2(*(__half2*)&u.y);
    acc.x += f0.x; acc.y += f0.y; acc.z += f1.x; acc.w += f1.y;
}

__global__ void __launch_bounds__(256)
gather_kernel(const float* __restrict__ bias, float* __restrict__ out, int N) {
    const int lane = threadIdx.x & 31;
    const int node = (blockIdx.x * blockDim.x + threadIdx.x) >> 5;
    if (node >= N) return;
    const int beg = g_off[node];
    const int end = g_off[node + 1];

    float4 acc = make_float4(0.f, 0.f, 0.f, 0.f);
    for (int b = beg; b < end; b += 32) {
        int idx = b + lane;
        int s = (idx < end) ? g_srcs[idx] : 0;
        int cnt = end - b; if (cnt > 32) cnt = 32;
        int j = 0;
        for (; j + 4 <= cnt; j += 4) {
            int s0 = __shfl_sync(0xffffffffu, s, j + 0);
            int s1 = __shfl_sync(0xffffffffu, s, j + 1);
            int s2 = __shfl_sync(0xffffffffu, s, j + 2);
            int s3 = __shfl_sync(0xffffffffu, s, j + 3);
            acc_row(acc, s0, lane);
            acc_row(acc, s1, lane);
            acc_row(acc, s2, lane);
            acc_row(acc, s3, lane);
        }
        for (; j < cnt; j++) {
            int sj = __shfl_sync(0xffffffffu, s, j);
            acc_row(acc, sj, lane);
        }
    }
    float4 b4 = *((const float4*)bias + lane);
    *((float4*)(out + (size_t)node * OUT_F) + lane) =
        make_float4(acc.x + b4.x, acc.y + b4.y, acc.z + b4.z, acc.w + b4.w);
}

// ---------------------------------------------------------------------------
extern "C" void kernel_launch(void* const* d_in, const int* in_sizes, int n_in,
                              void* d_out, int out_size) {
    const float* feat   = (const float*)d_in[0];
    const float* weight = (const float*)d_in[1];
    const float* bias   = (const float*)d_in[2];
    const int*   src    = (const int*)d_in[3];
    const int*   dst    = (const int*)d_in[4];
    float* out = (float*)d_out;

    const int N = in_sizes[0] / IN_F;   // 50000
    const int E = in_sizes[3];          // 800000
    const int nb = (N + SCAN_B - 1) / SCAN_B;

    cudaFuncSetAttribute(gemm_hmma_kernel,
                         cudaFuncAttributeMaxDynamicSharedMemorySize, GEMM_SMEM);

    init_kernel<<<256, 256>>>(N);
    edge_count_kernel<<<512, 256>>>(src, dst, E);
    wprep_kernel<<<(IN_F * OUT_F + 255) / 256, 256>>>(weight);
    scanA_kernel<<<nb, SCAN_B>>>(N);
    scanB_kernel<<<1, 64>>>(nb);
    scanC_kernel<<<nb, SCAN_B>>>(N, E);
    bucket_kernel<<<512, 256>>>(src, dst, E);
    gemm_hmma_kernel<<<(N + 127) / 128, 256, GEMM_SMEM>>>(feat, N);
    gather_kernel<<<(N * 32 + 255) / 256, 256>>>(bias, out, N);
}

// round 8
// speedup vs baseline: 1.8605x; 1.0041x over previous
#include <cuda_runtime.h>
#include <cuda_bf16.h>
#include <cuda_fp16.h>
#include <cstdint>

#define IN_F  256
#define OUT_F 128
#define MAX_N 50048
#define MAX_E 800000
#define SCAN_B 1024
#define SCAN_NB ((MAX_N + SCAN_B - 1) / SCAN_B)   // 49

// ---------------------------------------------------------------------------
// Scratch (static __device__ — no allocations allowed)
// ---------------------------------------------------------------------------
__device__ __align__(16) __half g_h[(size_t)MAX_N * OUT_F];  // normalized feats (fp16)
__device__ int   g_deg[MAX_N];
__device__ int   g_cnt[MAX_N];
__device__ int   g_off[MAX_N + 1];
__device__ int   g_pos[MAX_N];
__device__ int   g_srcs[MAX_E];
__device__ int   g_bsum[SCAN_NB];
__device__ __align__(16) unsigned short g_w0[IN_F * OUT_F];
__device__ __align__(16) unsigned short g_w1[IN_F * OUT_F];

// ---------------------------------------------------------------------------
__device__ __forceinline__ uint32_t smem_u32(const void* p) {
    uint32_t a;
    asm("{ .reg .u64 t; cvta.to.shared.u64 t, %1; cvt.u32.u64 %0, t; }" : "=r"(a) : "l"(p));
    return a;
}
__device__ __forceinline__ void ldm_x4(uint32_t* r, uint32_t addr) {
    asm volatile("ldmatrix.sync.aligned.m8n8.x4.shared.b16 {%0,%1,%2,%3}, [%4];"
                 : "=r"(r[0]), "=r"(r[1]), "=r"(r[2]), "=r"(r[3]) : "r"(addr));
}
__device__ __forceinline__ void ldm_x4_t(uint32_t* r, uint32_t addr) {
    asm volatile("ldmatrix.sync.aligned.m8n8.x4.trans.shared.b16 {%0,%1,%2,%3}, [%4];"
                 : "=r"(r[0]), "=r"(r[1]), "=r"(r[2]), "=r"(r[3]) : "r"(addr));
}
__device__ __forceinline__ void mma_bf16(float* d, const uint32_t* a, uint32_t b0, uint32_t b1) {
    asm volatile(
        "mma.sync.aligned.m16n8k16.row.col.f32.bf16.bf16.f32 "
        "{%0,%1,%2,%3}, {%4,%5,%6,%7}, {%8,%9}, {%0,%1,%2,%3};"
        : "+f"(d[0]), "+f"(d[1]), "+f"(d[2]), "+f"(d[3])
        : "r"(a[0]), "r"(a[1]), "r"(a[2]), "r"(a[3]), "r"(b0), "r"(b1));
}
__device__ __forceinline__ void split_bf16(float x, unsigned short& hi, unsigned short& lo) {
    __nv_bfloat16 h = __float2bfloat16_rn(x);
    float r = x - __bfloat162float(h);
    __nv_bfloat16 l = __float2bfloat16_rn(r);
    hi = __bfloat16_as_ushort(h);
    lo = __bfloat16_as_ushort(l);
}

// ---------------------------------------------------------------------------
// Kernel 1: zero counters + split W into bf16 hi/lo (fused independent prep)
// ---------------------------------------------------------------------------
__global__ void prep_kernel(const float* __restrict__ weight, int N) {
    int stride = gridDim.x * blockDim.x;
    int tid = blockIdx.x * blockDim.x + threadIdx.x;
    for (int i = tid; i < N; i += stride) { g_deg[i] = 0; g_cnt[i] = 0; }
    for (int i = tid; i < IN_F * OUT_F; i += stride) {
        unsigned short hi, lo;
        split_bf16(weight[i], hi, lo);
        g_w0[i] = hi;
        g_w1[i] = lo;
    }
}

// ---------------------------------------------------------------------------
// Kernel 2: out-degree(src) + in-degree(dst)
// ---------------------------------------------------------------------------
__global__ void edge_count_kernel(const int* __restrict__ src,
                                  const int* __restrict__ dst, int E) {
    int stride = gridDim.x * blockDim.x;
    for (int e = blockIdx.x * blockDim.x + threadIdx.x; e < E; e += stride) {
        atomicAdd(&g_deg[src[e]], 1);
        atomicAdd(&g_cnt[dst[e]], 1);
    }
}

// ---------------------------------------------------------------------------
// Kernel 3a: per-block exclusive scan of g_cnt (local) + block totals
// ---------------------------------------------------------------------------
__global__ void __launch_bounds__(SCAN_B)
scanA_kernel(int N) {
    __shared__ int wsum[32];
    int i = blockIdx.x * SCAN_B + threadIdx.x;
    int lane = threadIdx.x & 31, w = threadIdx.x >> 5;
    int v = (i < N) ? g_cnt[i] : 0;
    int inc = v;
#pragma unroll
    for (int o = 1; o < 32; o <<= 1) {
        int t = __shfl_up_sync(0xffffffffu, inc, o);
        if (lane >= o) inc += t;
    }
    if (lane == 31) wsum[w] = inc;
    __syncthreads();
    if (w == 0) {
        int x = wsum[lane];
#pragma unroll
        for (int o = 1; o < 32; o <<= 1) {
            int t = __shfl_up_sync(0xffffffffu, x, o);
            if (lane >= o) x += t;
        }
        wsum[lane] = x;
    }
    __syncthreads();
    int base = (w > 0) ? wsum[w - 1] : 0;
    int excl = base + inc - v;
    if (i < N) g_off[i] = excl;
    if (threadIdx.x == SCAN_B - 1) g_bsum[blockIdx.x] = base + inc;
}

// ---------------------------------------------------------------------------
// Kernel 3b: add block bases (computed inline from g_bsum); mirror into g_pos
// ---------------------------------------------------------------------------
__global__ void __launch_bounds__(SCAN_B)
scanC_kernel(int N, int E) {
    __shared__ int sbase;
    if (threadIdx.x < 32) {
        int sum = 0;
        for (int b = threadIdx.x; b < blockIdx.x; b += 32) sum += g_bsum[b];
#pragma unroll
        for (int o = 16; o > 0; o >>= 1)
            sum += __shfl_down_sync(0xffffffffu, sum, o);
        if (threadIdx.x == 0) sbase = sum;
    }
    __syncthreads();
    int i = blockIdx.x * SCAN_B + threadIdx.x;
    if (i < N) {
        int o = g_off[i] + sbase;
        g_off[i] = o;
        g_pos[i] = o;
    }
    if (i == 0) g_off[N] = E;
}

// ---------------------------------------------------------------------------
// Kernel 4: bucket src ids by dst
// ---------------------------------------------------------------------------
__global__ void bucket_kernel(const int* __restrict__ src,
                              const int* __restrict__ dst, int E) {
    int stride = gridDim.x * blockDim.x;
    for (int e = blockIdx.x * blockDim.x + threadIdx.x; e < E; e += stride) {
        int p = atomicAdd(&g_pos[dst[e]], 1);
        g_srcs[p] = src[e];
    }
}

// ---------------------------------------------------------------------------
// Kernel 5: HMMA GEMM  h = (feat @ W) * (1/max(deg,1)), fp16 output.
// Double-buffered smem, one __syncthreads per K-pass; A+B prefetched to regs
// before the MMA block, stored to the other buffer after it.
// ---------------------------------------------------------------------------
#define KT 64
#define SA0 0
#define SA1 16384
#define SB0 32768
#define SB1 49152
#define BUF 65536
#define GEMM_SMEM (2 * BUF)

__device__ __forceinline__ void load_a_regs(float4* va, const float* __restrict__ feat,
                                            int block_row, int k0, int tid, int N) {
#pragma unroll
    for (int i = 0; i < 8; i++) {
        int idx = i * 256 + tid;
        int r   = idx >> 4;
        int c4  = idx & 15;
        int grow = block_row + r;
        va[i] = make_float4(0.f, 0.f, 0.f, 0.f);
        if (grow < N)
            va[i] = *(const float4*)(feat + (size_t)grow * IN_F + k0 + c4 * 4);
    }
}
__device__ __forceinline__ void load_b_regs(uint2* vb0, uint2* vb1, int k0, int tid) {
#pragma unroll
    for (int i = 0; i < 8; i++) {
        int idx = i * 256 + tid;
        int k   = idx >> 5;
        int c8  = idx & 31;
        vb0[i] = *(const uint2*)&g_w0[(k0 + k) * OUT_F + c8 * 4];
        vb1[i] = *(const uint2*)&g_w1[(k0 + k) * OUT_F + c8 * 4];
    }
}
__device__ __forceinline__ void store_a(char* buf, const float4* va, int tid) {
#pragma unroll
    for (int i = 0; i < 8; i++) {
        int idx = i * 256 + tid;
        int r   = idx >> 4;
        int c4  = idx & 15;
        float4 v = va[i];
        unsigned short h0, h1, h2, h3, l0, l1, l2, l3;
        split_bf16(v.x, h0, l0); split_bf16(v.y, h1, l1);
        split_bf16(v.z, h2, l2); split_bf16(v.w, h3, l3);
        uint2 hv, lv;
        hv.x = (uint32_t)h0 | ((uint32_t)h1 << 16);
        hv.y = (uint32_t)h2 | ((uint32_t)h3 << 16);
        lv.x = (uint32_t)l0 | ((uint32_t)l1 << 16);
        lv.y = (uint32_t)l2 | ((uint32_t)l3 << 16);
        int chunk = c4 >> 1, half = c4 & 1;
        uint32_t off = (uint32_t)r * 128 + (uint32_t)((chunk ^ (r & 7)) << 4) + half * 8;
        *(uint2*)(buf + SA0 + off) = hv;
        *(uint2*)(buf + SA1 + off) = lv;
    }
}
__device__ __forceinline__ void store_b(char* buf, const uint2* vb0, const uint2* vb1, int tid) {
#pragma unroll
    for (int i = 0; i < 8; i++) {
        int idx = i * 256 + tid;
        int k   = idx >> 5;
        int c8  = idx & 31;
        int chunk = c8 >> 1, half = c8 & 1;
        uint32_t off = (uint32_t)k * 256 + (uint32_t)((chunk ^ (k & 7)) << 4) + half * 8;
        *(uint2*)(buf + SB0 + off) = vb0[i];
        *(uint2*)(buf + SB1 + off) = vb1[i];
    }
}

__global__ void __launch_bounds__(256)
gemm_hmma_kernel(const float* __restrict__ feat, int N) {
    extern __shared__ char smem[];
    const uint32_t sb = smem_u32(smem);
    const int tid  = threadIdx.x;
    const int wid  = tid >> 5;
    const int lane = tid & 31;
    const int mw   = wid & 3;
    const int nw   = wid >> 2;
    const int block_row = blockIdx.x * 128;

    float acc[2][8][4];
#pragma unroll
    for (int mt = 0; mt < 2; mt++)
#pragma unroll
        for (int g = 0; g < 8; g++)
#pragma unroll
            for (int c = 0; c < 4; c++) acc[mt][g][c] = 0.f;

    float4 va[8];
    uint2 vb0[8], vb1[8];
    load_a_regs(va, feat, block_row, 0, tid, N);
    load_b_regs(vb0, vb1, 0, tid);
    store_a(smem, va, tid);
    store_b(smem, vb0, vb1, tid);
    __syncthreads();

    for (int pass = 0; pass < 4; pass++) {
        const uint32_t sbc = sb + (uint32_t)(pass & 1) * BUF;

        // prefetch next pass into regs (latency hidden by MMA below)
        if (pass < 3) {
            load_a_regs(va, feat, block_row, (pass + 1) * KT, tid, N);
            load_b_regs(vb0, vb1, (pass + 1) * KT, tid);
        }

#pragma unroll
        for (int ks = 0; ks < 4; ks++) {
            uint32_t a0[2][4], a1[2][4];
#pragma unroll
            for (int mt = 0; mt < 2; mt++) {
                int row = mw * 32 + mt * 16 + (lane & 15);
                int chunk = ks * 2 + (lane >> 4);
                uint32_t off = (uint32_t)row * 128 + (uint32_t)((chunk ^ (row & 7)) << 4);
                ldm_x4(a0[mt], sbc + SA0 + off);
                ldm_x4(a1[mt], sbc + SA1 + off);
            }
            uint32_t b0[8][2], b1[8][2];
#pragma unroll
            for (int g16 = 0; g16 < 4; g16++) {
                int t = lane >> 3;
                int krow = ks * 16 + ((t & 1) << 3) + (lane & 7);
                int chunk = nw * 8 + g16 * 2 + (t >> 1);
                uint32_t off = (uint32_t)krow * 256 + (uint32_t)((chunk ^ (krow & 7)) << 4);
                uint32_t r0[4], r1[4];
                ldm_x4_t(r0, sbc + SB0 + off);
                ldm_x4_t(r1, sbc + SB1 + off);
                b0[g16 * 2 + 0][0] = r0[0]; b0[g16 * 2 + 0][1] = r0[1];
                b0[g16 * 2 + 1][0] = r0[2]; b0[g16 * 2 + 1][1] = r0[3];
                b1[g16 * 2 + 0][0] = r1[0]; b1[g16 * 2 + 0][1] = r1[1];
                b1[g16 * 2 + 1][0] = r1[2]; b1[g16 * 2 + 1][1] = r1[3];
            }
#pragma unroll
            for (int mt = 0; mt < 2; mt++)
#pragma unroll
                for (int g = 0; g < 8; g++) {
                    mma_bf16(acc[mt][g], a0[mt], b0[g][0], b0[g][1]);
                    mma_bf16(acc[mt][g], a0[mt], b1[g][0], b1[g][1]);
                    mma_bf16(acc[mt][g], a1[mt], b0[g][0], b0[g][1]);
                }
        }

        // store prefetched tiles into the other buffer (no barrier needed)
        if (pass < 3) {
            char* nxt = smem + ((pass + 1) & 1) * BUF;
            store_a(nxt, va, tid);
            store_b(nxt, vb0, vb1, tid);
        }
        __syncthreads();
    }

    // ---- epilogue: scale by 1/max(deg,1), store fp16 h ----
#pragma unroll
    for (int mt = 0; mt < 2; mt++) {
        int row0 = block_row + mw * 32 + mt * 16 + (lane >> 2);
        int row1 = row0 + 8;
        float n0 = (row0 < N) ? 1.0f / fmaxf((float)g_deg[row0], 1.0f) : 0.f;
        float n1 = (row1 < N) ? 1.0f / fmaxf((float)g_deg[row1], 1.0f) : 0.f;
#pragma unroll
        for (int g = 0; g < 8; g++) {
            int col = nw * 64 + g * 8 + (lane & 3) * 2;
            if (row0 < N)
                *(__half2*)(g_h + (size_t)row0 * OUT_F + col) =
                    __floats2half2_rn(acc[mt][g][0] * n0, acc[mt][g][1] * n0);
            if (row1 < N)
                *(__half2*)(g_h + (size_t)row1 * OUT_F + col) =
                    __floats2half2_rn(acc[mt][g][2] * n1, acc[mt][g][3] * n1);
        }
    }
}

// ---------------------------------------------------------------------------
// Kernel 6: gather  out[n] = sum_{e: dst=n} h[src[e]] + bias   (one warp/node)
// ---------------------------------------------------------------------------
__device__ __forceinline__ void acc_row(float4& acc, int s, int lane) {
    uint2 u = *((const uint2*)(g_h + (size_t)s * OUT_F) + lane);
    float2 f0 = __half22float2(*(__half2*)&u.x);
    float2 f1 = __half22float2(*(__half2*)&u.y);
    acc.x += f0.x; acc.y += f0.y; acc.z += f1.x; acc.w += f1.y;
}

__global__ void __launch_bounds__(256)
gather_kernel(const float* __restrict__ bias, float* __restrict__ out, int N) {
    const int lane = threadIdx.x & 31;
    const int node = (blockIdx.x * blockDim.x + threadIdx.x) >> 5;
    if (node >= N) return;
    const int beg = g_off[node];
    const int end = g_off[node + 1];

    float4 acc = make_float4(0.f, 0.f, 0.f, 0.f);
    for (int b = beg; b < end; b += 32) {
        int idx = b + lane;
        int s = (idx < end) ? g_srcs[idx] : 0;
        int cnt = end - b; if (cnt > 32) cnt = 32;
        int j = 0;
        for (; j + 4 <= cnt; j += 4) {
            int s0 = __shfl_sync(0xffffffffu, s, j + 0);
            int s1 = __shfl_sync(0xffffffffu, s, j + 1);
            int s2 = __shfl_sync(0xffffffffu, s, j + 2);
            int s3 = __shfl_sync(0xffffffffu, s, j + 3);
            acc_row(acc, s0, lane);
            acc_row(acc, s1, lane);
            acc_row(acc, s2, lane);
            acc_row(acc, s3, lane);
        }
        for (; j < cnt; j++) {
            int sj = __shfl_sync(0xffffffffu, s, j);
            acc_row(acc, sj, lane);
        }
    }
    float4 b4 = *((const float4*)bias + lane);
    *((float4*)(out + (size_t)node * OUT_F) + lane) =
        make_float4(acc.x + b4.x, acc.y + b4.y, acc.z + b4.z, acc.w + b4.w);
}

// ---------------------------------------------------------------------------
extern "C" void kernel_launch(void* const* d_in, const int* in_sizes, int n_in,
                              void* d_out, int out_size) {
    const float* feat   = (const float*)d_in[0];
    const float* weight = (const float*)d_in[1];
    const float* bias   = (const float*)d_in[2];
    const int*   src    = (const int*)d_in[3];
    const int*   dst    = (const int*)d_in[4];
    float* out = (float*)d_out;

    const int N = in_sizes[0] / IN_F;   // 50000
    const int E = in_sizes[3];          // 800000
    const int nb = (N + SCAN_B - 1) / SCAN_B;

    cudaFuncSetAttribute(gemm_hmma_kernel,
                         cudaFuncAttributeMaxDynamicSharedMemorySize, GEMM_SMEM);

    prep_kernel<<<256, 256>>>(weight, N);
    edge_count_kernel<<<512, 256>>>(src, dst, E);
    scanA_kernel<<<nb, SCAN_B>>>(N);
    scanC_kernel<<<nb, SCAN_B>>>(N, E);
    bucket_kernel<<<512, 256>>>(src, dst, E);
    gemm_hmma_kernel<<<(N + 127) / 128, 256, GEMM_SMEM>>>(feat, N);
    gather_kernel<<<(N * 32 + 255) / 256, 256>>>(bias, out, N);
}